// round 4
// baseline (speedup 1.0000x reference)
#include <cuda_runtime.h>

#define HH 1024
#define WW 1024
#define MM 512            // 16 segments * 32 samples
#define T_WIN 16.0f       // 32-px transition window; tail err <= e^-15 ~ 3e-7
#define KCAP 512

// Per-edge packed constants (phase A -> phase B)
__device__ float4 g_e1[MM];   // ymin, ymax, y0, rinv
__device__ float4 g_e2[MM];   // x0, dx, coeff, pad

// ---------------- Phase A: sample path, build edge tables ----------------
__global__ void bvr_prep_kernel(const float* __restrict__ cp)
{
    __shared__ float2 s_pts[MM];
    const int i = threadIdx.x;          // 512 threads

    {
        int s = i >> 5;
        int j = i & 31;
        float t  = (float)j / 31.0f;
        float mt = 1.0f - t;
        float w0 = mt * mt * mt;
        float w1 = 3.0f * mt * mt * t;
        float w2 = 3.0f * mt * t * t;
        float w3 = t * t * t;
        const float* p = cp + 6 * s;
        float px = w0 * p[0] + w1 * p[2] + w2 * p[4] + w3 * p[6];
        float py = w0 * p[1] + w1 * p[3] + w2 * p[5] + w3 * p[7];
        s_pts[i] = make_float2(px, py);
    }
    __syncthreads();

    float2 p0 = s_pts[i];
    float2 p1 = s_pts[(i + 1) & (MM - 1)];
    float dy = p1.y - p0.y;

    if (fabsf(dy) < 1e-6f) {
        g_e1[i] = make_float4(1e30f, -1e30f, 0.f, 0.f);   // impossible y-range
        g_e2[i] = make_float4(0.f, 0.f, 0.f, 0.f);
        return;
    }
    float coeff = (dy > 0.0f) ? 1.0f : -1.0f;
    float dx   = p1.x - p0.x;
    float rinv = 1.0f / (dy + 1e-8f);
    // |w| > ~1e-10 requires t in ~[-1.2, 2.2]
    float ya = p0.y - 1.2f * dy;
    float yb = p0.y + 2.2f * dy;
    g_e1[i] = make_float4(fminf(ya, yb), fmaxf(ya, yb), p0.y, rinv);
    g_e2[i] = make_float4(p0.x, dx, coeff, 0.f);
}

// ---------------- Phase B: one block per row ----------------
__global__ __launch_bounds__(256)
void bvr_render_kernel(const float* __restrict__ color,
                       float* __restrict__ out)
{
    __shared__ float  s_acc[WW];       // windowed sigmoid contributions
    __shared__ float  s_d[WW + 1];     // difference array: d[xlo] += w
    __shared__ float4 s_ek[KCAP];      // compacted: {w, xc, xlo(bits), pad}
    __shared__ float  s_part[256];
    __shared__ float  s_wsum[8];
    __shared__ float  s_tot;
    __shared__ int    s_cnt;

    const int tid = threadIdx.x;
    const int y   = blockIdx.x;
    const float fy = (float)y;

    if (tid == 0) { s_cnt = 0; s_tot = 0.0f; s_d[WW] = 0.0f; }
    for (int i = tid; i < WW; i += 256) { s_acc[i] = 0.0f; s_d[i] = 0.0f; }
    __syncthreads();

    // ---- compact active edges for this row ----
    #pragma unroll
    for (int it = 0; it < 2; ++it) {
        int e = tid + it * 256;
        float4 e1 = g_e1[e];                        // ymin, ymax, y0, rinv
        if (fy < e1.x || fy > e1.y) continue;       // most edges exit here

        float4 e2 = g_e2[e];                        // x0, dx, coeff
        float t   = (fy - e1.z) * e1.w;
        float v1  = 1.0f / (1.0f + __expf(-20.0f * t));
        float v2  = 1.0f / (1.0f + __expf(20.0f * (t - 1.0f)));
        float w   = e2.z * v1 * v2;
        if (fabsf(w) < 1e-10f) continue;

        float xc = e2.x + t * e2.y;
        if (xc + T_WIN < 0.0f) continue;            // sigmoid ~0 across whole row

        int xlo = (int)ceilf(xc - T_WIN);
        xlo = max(0, min(xlo, WW));

        atomicAdd(&s_d[xlo], w);
        atomicAdd(&s_tot, w);
        int k = atomicAdd(&s_cnt, 1);
        s_ek[k] = make_float4(w, xc, __int_as_float(xlo), 0.f);
    }
    __syncthreads();

    const int K = s_cnt;

    // ---- window work: warp-per-edge, lane = pixel offset (no div/mod) ----
    for (int i = tid; i < (K << 5); i += 256) {
        int k    = i >> 5;                          // warp-uniform
        int lane = i & 31;
        float4 ek = s_ek[k];                        // broadcast LDS.128
        int x = __float_as_int(ek.z) + lane;
        if (x < WW) {
            float val = __fdividef(ek.x, 1.0f + __expf((float)x - ek.y));
            atomicAdd(&s_acc[x], val);              // 32 consecutive addrs
        }
    }
    __syncthreads();

    // ---- inclusive scan of s_d; base[x] = tot - scan[x] ----
    const int b = tid * 4;
    float v0 = s_d[b];
    float v1 = v0 + s_d[b + 1];
    float v2 = v1 + s_d[b + 2];
    float v3 = v2 + s_d[b + 3];
    s_part[tid] = v3;
    __syncthreads();

    float pscan = s_part[tid];
    const int lane = tid & 31;
    const int wrp  = tid >> 5;
    #pragma unroll
    for (int off = 1; off < 32; off <<= 1) {
        float n = __shfl_up_sync(0xffffffffu, pscan, off);
        if (lane >= off) pscan += n;
    }
    if (lane == 31) s_wsum[wrp] = pscan;
    __syncthreads();
    if (tid == 0) {
        float r = 0.0f;
        #pragma unroll
        for (int i = 0; i < 8; ++i) { r += s_wsum[i]; s_wsum[i] = r; }
    }
    __syncthreads();
    float excl = ((wrp > 0) ? s_wsum[wrp - 1] : 0.0f) + pscan - v3;
    float tot  = s_tot;

    // ---- alpha + output ----
    float wind[4];
    wind[0] = (tot - (excl + v0)) + s_acc[b + 0];
    wind[1] = (tot - (excl + v1)) + s_acc[b + 1];
    wind[2] = (tot - (excl + v2)) + s_acc[b + 2];
    wind[3] = (tot - (excl + v3)) + s_acc[b + 3];

    const float cr = __ldg(color + 0);
    const float cg = __ldg(color + 1);
    const float cb = __ldg(color + 2);

    float4* orow = (float4*)out + (size_t)y * WW + b;
    #pragma unroll
    for (int q = 0; q < 4; ++q) {
        float a = 1.0f / (1.0f + __expf(-4.0f * wind[q]));
        orow[q] = make_float4(cr, cg, cb, a);
    }
}

extern "C" void kernel_launch(void* const* d_in, const int* in_sizes, int n_in,
                              void* d_out, int out_size)
{
    const float* cp    = (const float*)d_in[0];   // (49, 2) float32
    const float* color = (const float*)d_in[1];   // (3,)   float32
    float* out = (float*)d_out;                   // (1024, 1024, 4) float32
    (void)in_sizes; (void)n_in; (void)out_size;
    bvr_prep_kernel<<<1, MM>>>(cp);
    bvr_render_kernel<<<HH, 256>>>(color, out);
}

// round 5
// speedup vs baseline: 1.0861x; 1.0861x over previous
#include <cuda_runtime.h>

#define HH 1024
#define WW 1024
#define MM 512            // 16 segments * 32 samples
#define TW 16.0f          // sigmoid half-window; tail err sigma(16) ~ 1.1e-7
#define KCAP 512

__global__ __launch_bounds__(256)
void bvr_fused_kernel(const float* __restrict__ cp,
                      const float* __restrict__ color,
                      float* __restrict__ out)
{
    __shared__ float2 s_pts[MM];    // sampled path points
    __shared__ float2 s_wk[KCAP];   // compacted active edges: {w, xc}
    __shared__ int    s_cnt;

    const int tid = threadIdx.x;
    const int y   = blockIdx.x;
    const float fy = (float)y;

    if (tid == 0) s_cnt = 0;

    // ---- 1. Sample Bezier path (2 points per thread) ----
    #pragma unroll
    for (int it = 0; it < 2; ++it) {
        int i = tid + it * 256;
        int s = i >> 5;
        int j = i & 31;
        float t  = (float)j * (1.0f / 31.0f);
        float mt = 1.0f - t;
        float b0 = mt * mt * mt;
        float b1 = 3.0f * mt * mt * t;
        float b2 = 3.0f * mt * t * t;
        float b3 = t * t * t;
        const float* p = cp + 6 * s;
        float px = b0 * p[0] + b1 * p[2] + b2 * p[4] + b3 * p[6];
        float py = b0 * p[1] + b1 * p[3] + b2 * p[5] + b3 * p[7];
        s_pts[i] = make_float2(px, py);
    }
    __syncthreads();

    // ---- 2. Compact active edges for this row ----
    #pragma unroll
    for (int it = 0; it < 2; ++it) {
        int e = tid + it * 256;
        float2 p0 = s_pts[e];
        float2 p1 = s_pts[(e + 1) & (MM - 1)];
        float dy = p1.y - p0.y;
        if (fabsf(dy) < 1e-6f) continue;          // coeff == 0 in reference

        // |w| > ~1e-10 requires t in ~[-1.2, 2.2]; cheap reject (no div)
        float ba = p0.y - 1.2f * dy;
        float bb = p0.y + 2.2f * dy;
        if (fy < fminf(ba, bb) || fy > fmaxf(ba, bb)) continue;

        float t  = (fy - p0.y) / (dy + 1e-8f);    // matches reference
        float v1 = 1.0f / (1.0f + __expf(-20.0f * t));
        float v2 = 1.0f / (1.0f + __expf(20.0f * (t - 1.0f)));
        float coeff = (dy > 0.0f) ? 1.0f : -1.0f;
        float w  = coeff * v1 * v2;
        if (fabsf(w) < 1e-10f) continue;

        float xc = p0.x + t * (p1.x - p0.x);
        if (xc < -TW) continue;                   // sigma ~0 across whole row

        int k = atomicAdd(&s_cnt, 1);
        s_wk[k] = make_float2(w, xc);
    }
    __syncthreads();

    const int K = s_cnt;
    const float x0 = (float)(tid * 4);            // this thread's first pixel

    // ---- 3. Combined base + window accumulation (no atomics, no scatter) ----
    float wbase = 0.0f;                           // contributions equal on all 4 px
    float wa[4] = {0.f, 0.f, 0.f, 0.f};

    for (int k = 0; k < K; ++k) {
        float2 wk = s_wk[k];                      // LDS.64 broadcast
        float u0 = wk.y - x0;                     // xc - x  for pixel 0
        if (u0 - 3.0f >= TW) {                    // whole 4-px group deep inside
            wbase += wk.x;
        } else if (u0 > -TW) {                    // transition overlaps this group
            #pragma unroll
            for (int q = 0; q < 4; ++q) {
                float u = u0 - (float)q;
                float c;
                if (u >= TW)       c = wk.x;
                else if (u <= -TW) c = 0.0f;
                else c = __fdividef(wk.x, 1.0f + __expf(-u));
                wa[q] += c;
            }
        }
        // else: whole group right of the edge's transition -> 0
    }

    // ---- 4. Alpha + output ----
    const float cr = __ldg(color + 0);
    const float cg = __ldg(color + 1);
    const float cb = __ldg(color + 2);

    float4* orow = (float4*)out + (size_t)y * WW + tid * 4;
    #pragma unroll
    for (int q = 0; q < 4; ++q) {
        float wind = wbase + wa[q];
        float a = 1.0f / (1.0f + __expf(-4.0f * wind));
        orow[q] = make_float4(cr, cg, cb, a);
    }
}

extern "C" void kernel_launch(void* const* d_in, const int* in_sizes, int n_in,
                              void* d_out, int out_size)
{
    const float* cp    = (const float*)d_in[0];   // (49, 2) float32
    const float* color = (const float*)d_in[1];   // (3,)   float32
    float* out = (float*)d_out;                   // (1024, 1024, 4) float32
    (void)in_sizes; (void)n_in; (void)out_size;
    bvr_fused_kernel<<<HH, 256>>>(cp, color, out);
}

// round 6
// speedup vs baseline: 1.2145x; 1.1182x over previous
#include <cuda_runtime.h>

#define HH 1024
#define WW 1024
#define MM 512            // 16 segments * 32 samples
#define TW 16.0f          // sigmoid half-window; tail err sigma(-16) ~ 1.1e-7
#define KCAP 512
#define NT 128            // threads per block
#define PXT 8             // pixels per thread (warp covers 256 px)

// Per-edge packed constants (phase A -> phase B)
__device__ float4 g_e1[MM];   // ymin, ymax, y0, rinv
__device__ float4 g_e2[MM];   // x0, dx, coeff, pad

// ---------------- Phase A: sample path, build edge tables ----------------
__global__ void bvr_prep_kernel(const float* __restrict__ cp)
{
    __shared__ float2 s_pts[MM];
    const int i = threadIdx.x;          // 512 threads

    {
        int s = i >> 5;
        int j = i & 31;
        float t  = (float)j * (1.0f / 31.0f);
        float mt = 1.0f - t;
        float b0 = mt * mt * mt;
        float b1 = 3.0f * mt * mt * t;
        float b2 = 3.0f * mt * t * t;
        float b3 = t * t * t;
        const float* p = cp + 6 * s;
        float px = b0 * p[0] + b1 * p[2] + b2 * p[4] + b3 * p[6];
        float py = b0 * p[1] + b1 * p[3] + b2 * p[5] + b3 * p[7];
        s_pts[i] = make_float2(px, py);
    }
    __syncthreads();

    float2 p0 = s_pts[i];
    float2 p1 = s_pts[(i + 1) & (MM - 1)];
    float dy = p1.y - p0.y;

    if (fabsf(dy) < 1e-6f) {
        g_e1[i] = make_float4(1e30f, -1e30f, 0.f, 0.f);   // impossible y-range
        g_e2[i] = make_float4(0.f, 0.f, 0.f, 0.f);
        return;
    }
    float coeff = (dy > 0.0f) ? 1.0f : -1.0f;
    float dx   = p1.x - p0.x;
    float rinv = 1.0f / (dy + 1e-8f);
    // |w| > ~1e-10 requires t in ~[-1.2, 2.2]
    float ya = p0.y - 1.2f * dy;
    float yb = p0.y + 2.2f * dy;
    g_e1[i] = make_float4(fminf(ya, yb), fmaxf(ya, yb), p0.y, rinv);
    g_e2[i] = make_float4(p0.x, dx, coeff, 0.f);
}

// ---------------- Phase B: one block (128 threads) per row ----------------
__global__ __launch_bounds__(NT)
void bvr_render_kernel(const float* __restrict__ color,
                       float* __restrict__ out)
{
    __shared__ float  s_acc[WW];          // windowed sigmoid contributions
    __shared__ float2 s_bk[5][KCAP];      // per-bucket edge list: {w, xlo}
    __shared__ float2 s_wk[KCAP];         // window list: {w, xc}
    __shared__ int    s_bcnt[5];
    __shared__ float  s_btot[5];
    __shared__ int    s_cnt;

    const int tid = threadIdx.x;
    const int y   = blockIdx.x;
    const float fy = (float)y;

    if (tid < 5) { s_bcnt[tid] = 0; s_btot[tid] = 0.0f; }
    if (tid == 0) s_cnt = 0;
    #pragma unroll
    for (int it = 0; it < WW / NT; ++it) s_acc[tid + it * NT] = 0.0f;
    __syncthreads();

    // ---- compact active edges into window list + xlo buckets ----
    #pragma unroll
    for (int it = 0; it < MM / NT; ++it) {
        int e = tid + it * NT;
        float4 e1 = g_e1[e];                        // ymin, ymax, y0, rinv
        if (fy < e1.x || fy > e1.y) continue;       // most edges exit here

        float4 e2 = g_e2[e];                        // x0, dx, coeff
        float t   = (fy - e1.z) * e1.w;
        float v1  = 1.0f / (1.0f + __expf(-20.0f * t));
        float v2  = 1.0f / (1.0f + __expf(20.0f * (t - 1.0f)));
        float w   = e2.z * v1 * v2;
        if (fabsf(w) < 1e-10f) continue;

        float xc = e2.x + t * e2.y;
        if (xc < -TW) continue;                     // sigma ~0 across whole row

        int xlo = (int)ceilf(xc - TW);
        xlo = max(0, min(xlo, WW));

        int k = atomicAdd(&s_cnt, 1);
        s_wk[k] = make_float2(w, xc);

        int bkt  = xlo >> 8;                        // 0..3 warp ranges, 4 = full row
        int slot = atomicAdd(&s_bcnt[bkt], 1);
        s_bk[bkt][slot] = make_float2(w, (float)xlo);
        atomicAdd(&s_btot[bkt], w);
    }
    __syncthreads();

    const int K = s_cnt;

    // ---- window scatter: warp-per-edge, lane = pixel offset ----
    for (int i = tid; i < (K << 5); i += NT) {
        int k    = i >> 5;
        int lane = i & 31;
        float2 wk = s_wk[k];                        // {w, xc} broadcast
        int xlo = max(0, (int)ceilf(wk.y - TW));
        int x = xlo + lane;
        if (x < WW) {
            float val = __fdividef(wk.x, 1.0f + __expf((float)x - wk.y));
            atomicAdd(&s_acc[x], val);
        }
    }
    __syncthreads();

    // ---- base: suffix sum of higher buckets + own-bucket per-pixel step ----
    const int wrp = tid >> 5;                       // 0..3, covers px [wrp*256, +256)
    float wbase = 0.0f;
    #pragma unroll
    for (int j = 1; j <= 4; ++j)
        if (j > wrp) wbase += s_btot[j];

    float wa[PXT];
    #pragma unroll
    for (int q = 0; q < PXT; ++q) wa[q] = 0.0f;

    const float bf = (float)(tid * PXT);            // first pixel of this thread
    const int cnt_own = s_bcnt[wrp];
    for (int s = 0; s < cnt_own; ++s) {
        float2 ek = s_bk[wrp][s];                   // warp-uniform -> broadcast
        float m = ek.y - bf;                        // xlo - first px
        #pragma unroll
        for (int q = 0; q < PXT; ++q)
            wa[q] += ((float)q < m) ? ek.x : 0.0f;  // predicated, branch-free
    }

    // ---- alpha + output (8 px per thread) ----
    const float cr = __ldg(color + 0);
    const float cg = __ldg(color + 1);
    const float cb = __ldg(color + 2);

    float4* orow = (float4*)out + (size_t)y * WW + tid * PXT;
    #pragma unroll
    for (int q = 0; q < PXT; ++q) {
        float wind = wbase + wa[q] + s_acc[tid * PXT + q];
        float a = 1.0f / (1.0f + __expf(-4.0f * wind));
        orow[q] = make_float4(cr, cg, cb, a);
    }
}

extern "C" void kernel_launch(void* const* d_in, const int* in_sizes, int n_in,
                              void* d_out, int out_size)
{
    const float* cp    = (const float*)d_in[0];   // (49, 2) float32
    const float* color = (const float*)d_in[1];   // (3,)   float32
    float* out = (float*)d_out;                   // (1024, 1024, 4) float32
    (void)in_sizes; (void)n_in; (void)out_size;
    bvr_prep_kernel<<<1, MM>>>(cp);
    bvr_render_kernel<<<HH, NT>>>(color, out);
}

// round 7
// speedup vs baseline: 1.5265x; 1.2569x over previous
#include <cuda_runtime.h>

#define HH 1024
#define WW 1024
#define MM 512            // 16 segments * 32 samples
#define TW 16.0f          // sigmoid half-window; tail err ~1.1e-7
#define KCAP 128          // max active edges per row (observed ~26)
#define BCAP 128          // max edges per 128-px bucket
#define NT 256

__global__ __launch_bounds__(NT)
void bvr_fused_kernel(const float* __restrict__ cp,
                      const float* __restrict__ color,
                      float* __restrict__ out)
{
    __shared__ float2 s_pts[MM];        // sampled path points
    __shared__ float  s_acc[WW];        // windowed sigmoid contributions
    __shared__ float2 s_wk[KCAP];       // window list: {w, xc}
    __shared__ float2 s_bk[9][BCAP];    // bucket lists: {w, xlo}
    __shared__ int    s_bcnt[9];
    __shared__ float  s_btot[9];
    __shared__ int    s_cnt;

    const int tid = threadIdx.x;
    const int y   = blockIdx.x;
    const float fy = (float)y;

    if (tid < 9) { s_bcnt[tid] = 0; s_btot[tid] = 0.0f; }
    if (tid == 0) s_cnt = 0;
    #pragma unroll
    for (int it = 0; it < WW / NT; ++it) s_acc[tid + it * NT] = 0.0f;

    // ---- 1. Sample Bezier path (2 points per thread) ----
    #pragma unroll
    for (int it = 0; it < 2; ++it) {
        int i = tid + it * NT;
        int s = i >> 5;
        int j = i & 31;
        float t  = (float)j / 31.0f;
        float mt = 1.0f - t;
        float b0 = mt * mt * mt;
        float b1 = 3.0f * mt * mt * t;
        float b2 = 3.0f * mt * t * t;
        float b3 = t * t * t;
        const float* p = cp + 6 * s;
        float px = b0 * p[0] + b1 * p[2] + b2 * p[4] + b3 * p[6];
        float py = b0 * p[1] + b1 * p[3] + b2 * p[5] + b3 * p[7];
        s_pts[i] = make_float2(px, py);
    }
    __syncthreads();

    // ---- 2. Compact active edges for this row into window list + buckets ----
    #pragma unroll
    for (int it = 0; it < 2; ++it) {
        int e = tid + it * NT;
        float2 p0 = s_pts[e];
        float2 p1 = s_pts[(e + 1) & (MM - 1)];
        float dy = p1.y - p0.y;
        if (fabsf(dy) < 1e-6f) continue;            // coeff == 0 in reference

        // |w| > ~1e-10 requires t in ~[-1.2, 2.2]; cheap reject
        float ba = p0.y - 1.2f * dy;
        float bb = p0.y + 2.2f * dy;
        if (fy < fminf(ba, bb) || fy > fmaxf(ba, bb)) continue;

        float t  = __fdividef(fy - p0.y, dy + 1e-8f);
        float v1 = 1.0f / (1.0f + __expf(-20.0f * t));
        float v2 = 1.0f / (1.0f + __expf(20.0f * (t - 1.0f)));
        float coeff = (dy > 0.0f) ? 1.0f : -1.0f;
        float w  = coeff * v1 * v2;
        if (fabsf(w) < 1e-10f) continue;

        float xc = p0.x + t * (p1.x - p0.x);
        if (xc < -TW) continue;                     // ~0 across whole row

        int xlo = (int)ceilf(xc - TW);
        xlo = max(0, min(xlo, WW));

        int k = atomicAdd(&s_cnt, 1);
        s_wk[k] = make_float2(w, xc);

        int bkt  = xlo >> 7;                        // 0..7 = 128-px bands, 8 = full row
        int slot = atomicAdd(&s_bcnt[bkt], 1);
        s_bk[bkt][slot] = make_float2(w, (float)xlo);
        atomicAdd(&s_btot[bkt], w);
    }
    __syncthreads();

    const int K = s_cnt;

    // ---- 3a. Window scatter: warp-per-edge, lane = pixel offset ----
    for (int i = tid; i < (K << 5); i += NT) {
        int k    = i >> 5;                          // warp-uniform
        int lane = i & 31;
        float2 wk = s_wk[k];                        // broadcast LDS.64
        int x = max(0, (int)ceilf(wk.y - TW)) + lane;
        if (x < WW) {
            float val = __fdividef(wk.x, 1.0f + __expf((float)x - wk.y));
            atomicAdd(&s_acc[x], val);              // 32 consecutive addrs
        }
    }

    // ---- 3b. Base: suffix of higher buckets + own-bucket per-pixel step ----
    const int wrp = tid >> 5;                       // warp covers px [wrp*128, +128)
    float wbase = 0.0f;
    #pragma unroll
    for (int j = 1; j <= 8; ++j)
        wbase += (j > wrp) ? s_btot[j] : 0.0f;      // predicated

    float wa0 = 0.f, wa1 = 0.f, wa2 = 0.f, wa3 = 0.f;
    const float bf = (float)(tid * 4);              // this thread's first pixel
    const int cnt_own = s_bcnt[wrp];                // warp-uniform
    for (int s = 0; s < cnt_own; ++s) {
        float2 ek = s_bk[wrp][s];                   // broadcast LDS.64
        float m = ek.y - bf;                        // xlo - first px
        wa0 += (0.0f < m) ? ek.x : 0.0f;
        wa1 += (1.0f < m) ? ek.x : 0.0f;
        wa2 += (2.0f < m) ? ek.x : 0.0f;
        wa3 += (3.0f < m) ? ek.x : 0.0f;
    }
    __syncthreads();

    // ---- 4. Alpha + output ----
    const float cr = __ldg(color + 0);
    const float cg = __ldg(color + 1);
    const float cb = __ldg(color + 2);

    const int b = tid * 4;
    float wind[4];
    wind[0] = wbase + wa0 + s_acc[b + 0];
    wind[1] = wbase + wa1 + s_acc[b + 1];
    wind[2] = wbase + wa2 + s_acc[b + 2];
    wind[3] = wbase + wa3 + s_acc[b + 3];

    float4* orow = (float4*)out + (size_t)y * WW + b;
    #pragma unroll
    for (int q = 0; q < 4; ++q) {
        float a = 1.0f / (1.0f + __expf(-4.0f * wind[q]));
        orow[q] = make_float4(cr, cg, cb, a);
    }
}

extern "C" void kernel_launch(void* const* d_in, const int* in_sizes, int n_in,
                              void* d_out, int out_size)
{
    const float* cp    = (const float*)d_in[0];   // (49, 2) float32
    const float* color = (const float*)d_in[1];   // (3,)   float32
    float* out = (float*)d_out;                   // (1024, 1024, 4) float32
    (void)in_sizes; (void)n_in; (void)out_size;
    bvr_fused_kernel<<<HH, NT>>>(cp, color, out);
}

// round 10
// speedup vs baseline: 1.5496x; 1.0151x over previous
#include <cuda_runtime.h>

#define HH 1024
#define WW 1024
#define MM 512            // 16 segments * 32 samples
#define TW 16.0f          // sigmoid half-window; tail err ~1.1e-7
#define KCAP 128          // max active edges per row (observed ~26)
#define BCAP 128          // max edges per 128-px bucket
#define NT 256

__global__ __launch_bounds__(NT)
void bvr_fused_kernel(const float* __restrict__ cp,
                      const float* __restrict__ color,
                      float* __restrict__ out)
{
    __shared__ float2 s_pts[MM];        // sampled path points
    __shared__ float  s_acc[WW];        // windowed sigmoid contributions
    __shared__ float4 s_wk[KCAP];       // window list: {w, f=exp(xlo-xc), xlo, -}
    __shared__ float2 s_bk[9][BCAP];    // bucket lists: {w, xlo}
    __shared__ int    s_bcnt[9];
    __shared__ float  s_btot[9];
    __shared__ int    s_cnt;

    const int tid  = threadIdx.x;
    const int lane = tid & 31;
    const int y    = blockIdx.x;
    const float fy = (float)y;
    const float elane = __expf((float)lane);    // e^lane, one MUFU per thread

    if (tid < 9) { s_bcnt[tid] = 0; s_btot[tid] = 0.0f; }
    if (tid == 0) s_cnt = 0;
    #pragma unroll
    for (int it = 0; it < WW / NT; ++it) s_acc[tid + it * NT] = 0.0f;

    // ---- 1. Sample Bezier path (2 points per thread) ----
    #pragma unroll
    for (int it = 0; it < 2; ++it) {
        int i = tid + it * NT;
        int s = i >> 5;
        int j = i & 31;
        float t  = (float)j / 31.0f;
        float mt = 1.0f - t;
        float b0 = mt * mt * mt;
        float b1 = 3.0f * mt * mt * t;
        float b2 = 3.0f * mt * t * t;
        float b3 = t * t * t;
        const float* p = cp + 6 * s;
        float px = b0 * p[0] + b1 * p[2] + b2 * p[4] + b3 * p[6];
        float py = b0 * p[1] + b1 * p[3] + b2 * p[5] + b3 * p[7];
        s_pts[i] = make_float2(px, py);
    }
    __syncthreads();

    // ---- 2. Compact active edges into window list + xlo buckets ----
    #pragma unroll
    for (int it = 0; it < 2; ++it) {
        int e = tid + it * NT;
        float2 p0 = s_pts[e];
        float2 p1 = s_pts[(e + 1) & (MM - 1)];
        float dy = p1.y - p0.y;
        if (fabsf(dy) < 1e-6f) continue;            // coeff == 0 in reference

        float ba = p0.y - 1.2f * dy;                // |w|>1e-10 needs t in [-1.2,2.2]
        float bb = p0.y + 2.2f * dy;
        if (fy < fminf(ba, bb) || fy > fmaxf(ba, bb)) continue;

        float t  = __fdividef(fy - p0.y, dy + 1e-8f);
        float v1 = 1.0f / (1.0f + __expf(-20.0f * t));
        float v2 = 1.0f / (1.0f + __expf(20.0f * (t - 1.0f)));
        float coeff = (dy > 0.0f) ? 1.0f : -1.0f;
        float w  = coeff * v1 * v2;
        if (fabsf(w) < 1e-10f) continue;

        float xc = p0.x + t * (p1.x - p0.x);
        if (xc < -TW) continue;                     // ~0 across whole row

        int xlo = (int)ceilf(xc - TW);
        xlo = max(0, min(xlo, WW));
        float f = __expf((float)xlo - xc);          // window base factor

        int k = atomicAdd(&s_cnt, 1);
        s_wk[k] = make_float4(w, f, (float)xlo, 0.f);

        int bkt  = xlo >> 7;                        // 0..7 = 128-px bands, 8 = full row
        int slot = atomicAdd(&s_bcnt[bkt], 1);
        s_bk[bkt][slot] = make_float2(w, (float)xlo);
        atomicAdd(&s_btot[bkt], w);
    }
    __syncthreads();

    const int K = s_cnt;

    // ---- 3a. Window scatter: warp-per-edge, lane = px offset (1 MUFU/item) ----
    for (int i = tid; i < (K << 5); i += NT) {
        int k = i >> 5;                             // warp-uniform
        float4 wk = s_wk[k];                        // broadcast LDS.128
        int x = (int)wk.z + lane;
        if (x < WW) {
            // exp(x - xc) = elane * exp(xlo - xc)
            float val = __fdividef(wk.x, fmaf(elane, wk.y, 1.0f));
            atomicAdd(&s_acc[x], val);              // 32 consecutive addrs
        }
    }

    // ---- 3b. Base: suffix of higher buckets + own-bucket per-pixel step ----
    const int wrp = tid >> 5;                       // warp covers px [wrp*128, +128)
    float wbase = 0.0f;
    #pragma unroll
    for (int j = 1; j <= 8; ++j)
        wbase += (j > wrp) ? s_btot[j] : 0.0f;      // predicated

    float wa0 = 0.f, wa1 = 0.f, wa2 = 0.f, wa3 = 0.f;
    const float bf = (float)(tid * 4);              // this thread's first pixel
    const int cnt_own = s_bcnt[wrp];                // warp-uniform
    for (int s = 0; s < cnt_own; ++s) {
        float2 ek = s_bk[wrp][s];                   // broadcast LDS.64
        float m = ek.y - bf;                        // xlo - first px
        wa0 += (0.0f < m) ? ek.x : 0.0f;
        wa1 += (1.0f < m) ? ek.x : 0.0f;
        wa2 += (2.0f < m) ? ek.x : 0.0f;
        wa3 += (3.0f < m) ? ek.x : 0.0f;
    }
    __syncthreads();

    // ---- 4. Alpha via tanh.approx (1 MUFU/px) + output ----
    const float cr = __ldg(color + 0);
    const float cg = __ldg(color + 1);
    const float cb = __ldg(color + 2);

    const int b = tid * 4;
    float wind[4];
    wind[0] = wbase + wa0 + s_acc[b + 0];
    wind[1] = wbase + wa1 + s_acc[b + 1];
    wind[2] = wbase + wa2 + s_acc[b + 2];
    wind[3] = wbase + wa3 + s_acc[b + 3];

    float4* orow = (float4*)out + (size_t)y * WW + b;
    #pragma unroll
    for (int q = 0; q < 4; ++q) {
        // sigmoid(4w) = 0.5 + 0.5*tanh(2w)
        float th;
        asm("tanh.approx.f32 %0, %1;" : "=f"(th) : "f"(2.0f * wind[q]));
        float a = fmaf(0.5f, th, 0.5f);
        orow[q] = make_float4(cr, cg, cb, a);
    }
}

extern "C" void kernel_launch(void* const* d_in, const int* in_sizes, int n_in,
                              void* d_out, int out_size)
{
    const float* cp    = (const float*)d_in[0];   // (49, 2) float32
    const float* color = (const float*)d_in[1];   // (3,)   float32
    float* out = (float*)d_out;                   // (1024, 1024, 4) float32
    (void)in_sizes; (void)n_in; (void)out_size;
    bvr_fused_kernel<<<HH, NT>>>(cp, color, out);
}